// round 6
// baseline (speedup 1.0000x reference)
#include <cuda_runtime.h>
#include <cuda_fp16.h>
#include <cstdint>

#define NNODES 50000
#define NEDGES 850000
#define IN_DIM 256
#define HID 32
#define H1 8
#define OUT_DIM 64
#define HD1 (H1*HID)   // 256
#define KDIM 256

// ---------------- scratch ----------------
__device__ __align__(16) __half g_feat1h[NNODES * HD1];   // 25.6 MB fp16
__device__ __align__(16) float  g_h1[NNODES * HD1];       // 51.2 MB
__device__ __align__(16) float  g_feat2[NNODES * OUT_DIM];
__device__ __align__(16) float  g_el1[NNODES * H1];
__device__ __align__(16) float  g_er1[NNODES * H1];
__device__ __align__(16) float  g_el2[NNODES];
__device__ __align__(16) float  g_er2[NNODES];
__device__ __align__(16) int    g_cnt[NNODES];
__device__ __align__(16) int    g_off[NNODES + 1];
__device__ __align__(16) int    g_cur[NNODES];
__device__ __align__(16) int    g_csr_src[NEDGES];

// packed f32x2 FMA: d.lo += a.lo*b.lo ; d.hi += a.hi*b.hi
#define FMA_X2(d, a, b) \
    asm("fma.rn.f32x2 %0, %1, %2, %0;" : "+l"(d) : "l"(a), "l"(b))

__device__ __forceinline__ uint32_t h2_bits(__half2 h) {
    uint32_t u;
    memcpy(&u, &h, 4);
    return u;
}

// ---------------- packed-fp32 GEMM + fused attention epilogue ----------------
// C tile: rows [by*128, +128), cols [bx*64, +64). K = 256.
// 256 threads; thread microtile = 4 rows x 8 cols.
// LAYER 1: C -> __half g_feat1h (row stride 256), el1/er1 per 32-col head.
// LAYER 2: C -> float Cout (row stride 64), el2/er2 whole row.
#define BMT 128
#define BNT 64
#define BKT 32
#define AS2_STRIDE (2*BMT + 8)   // 264 floats
#define BS_STRIDE  (BNT + 4)     // 68 floats

template <int LAYER>
__global__ __launch_bounds__(256) void pgemm_kernel(
    const float* __restrict__ A, int M, int Nc,
    const float* __restrict__ B,          // [K=256][Nc] row-major
    void* __restrict__ Cout,
    const float* __restrict__ al, const float* __restrict__ ar)
{
    __shared__ float As2[BKT][AS2_STRIDE];   // duplicated: row r value at [2r],[2r+1]
    __shared__ float Bs[BKT][BS_STRIDE];

    const int tid = threadIdx.x;
    const int tr = tid >> 3;        // 0..31 -> rows tr*4..tr*4+3
    const int tc = tid & 7;         // 0..7  -> cols tc*8..tc*8+7
    const int blockRow = blockIdx.y * BMT;
    const int colbase = blockIdx.x * BNT;

    // A-load mapping: 8 threads per row, 4 row-batches of 32
    const int a_koff = (tid & 7) * 4;
    const int a_row0 = tid >> 3;          // 0..31

    unsigned long long acc[4][4];
#pragma unroll
    for (int i = 0; i < 4; i++)
#pragma unroll
        for (int j = 0; j < 4; j++) acc[i][j] = 0ull;

    for (int k0 = 0; k0 < KDIM; k0 += BKT) {
        // ---- A tile: 128 x 32, fully coalesced (full 128B lines per warp) ----
#pragma unroll
        for (int it = 0; it < 4; it++) {
            int row = a_row0 + it * 32;
            int gr = blockRow + row;
            float4 v = (gr < M) ? *(const float4*)(A + (size_t)gr * KDIM + k0 + a_koff)
                                : make_float4(0.f, 0.f, 0.f, 0.f);
            const float* vv = (const float*)&v;
#pragma unroll
            for (int j = 0; j < 4; j++)
                *(float2*)&As2[a_koff + j][2 * row] = make_float2(vv[j], vv[j]);
        }
        // ---- B tile: 32 x 64, coalesced ----
#pragma unroll
        for (int q = 0; q < 2; q++) {
            int i = tid + q * 256;
            int row = i >> 4, c4 = (i & 15) * 4;
            float4 v = *(const float4*)&B[(size_t)(k0 + row) * Nc + colbase + c4];
            *(float4*)&Bs[row][c4] = v;
        }
        __syncthreads();

#pragma unroll
        for (int kk = 0; kk < BKT; kk++) {
            unsigned long long a4[4], b4[4];
            {
                ulonglong2 t0 = *(const ulonglong2*)&As2[kk][2 * (tr * 4)];
                ulonglong2 t1 = *(const ulonglong2*)&As2[kk][2 * (tr * 4) + 4];
                a4[0] = t0.x; a4[1] = t0.y; a4[2] = t1.x; a4[3] = t1.y;
            }
            {
                ulonglong2 u0 = *(const ulonglong2*)&Bs[kk][tc * 8];
                ulonglong2 u1 = *(const ulonglong2*)&Bs[kk][tc * 8 + 4];
                b4[0] = u0.x; b4[1] = u0.y; b4[2] = u1.x; b4[3] = u1.y;
            }
#pragma unroll
            for (int i = 0; i < 4; i++)
#pragma unroll
                for (int j = 0; j < 4; j++)
                    FMA_X2(acc[i][j], a4[i], b4[j]);
        }
        __syncthreads();
    }

    // ---- epilogue: store C + fused el/er ----
    const int c0 = colbase + tc * 8;
    float alr[8], arr[8];
#pragma unroll
    for (int j = 0; j < 8; j++) { alr[j] = al[c0 + j]; arr[j] = ar[c0 + j]; }

    float elp[4], erp[4];
#pragma unroll
    for (int i = 0; i < 4; i++) {
        const int r = blockRow + tr * 4 + i;
        float c[8];
#pragma unroll
        for (int j = 0; j < 4; j++) {
            uint2 u = *(uint2*)&acc[i][j];
            c[2 * j] = __uint_as_float(u.x);
            c[2 * j + 1] = __uint_as_float(u.y);
        }
        float el = 0.f, er = 0.f;
#pragma unroll
        for (int j = 0; j < 8; j++) { el += c[j] * alr[j]; er += c[j] * arr[j]; }
        elp[i] = el; erp[i] = er;

        if (r < M) {
            if (LAYER == 1) {
                __half2 p0 = __floats2half2_rn(c[0], c[1]);
                __half2 p1 = __floats2half2_rn(c[2], c[3]);
                __half2 p2 = __floats2half2_rn(c[4], c[5]);
                __half2 p3 = __floats2half2_rn(c[6], c[7]);
                uint4 w = make_uint4(h2_bits(p0), h2_bits(p1), h2_bits(p2), h2_bits(p3));
                *(uint4*)&g_feat1h[(size_t)r * HD1 + c0] = w;
            } else {
                float* crow = (float*)Cout + (size_t)r * OUT_DIM + c0;
                *(float4*)crow = make_float4(c[0], c[1], c[2], c[3]);
                *(float4*)(crow + 4) = make_float4(c[4], c[5], c[6], c[7]);
            }
        }
    }

    if (LAYER == 1) {
        // head = bx*2 + (tc>>2); reduce within 4-lane groups (xor 1,2)
#pragma unroll
        for (int i = 0; i < 4; i++) {
#pragma unroll
            for (int o = 1; o <= 2; o <<= 1) {
                elp[i] += __shfl_xor_sync(0xffffffffu, elp[i], o);
                erp[i] += __shfl_xor_sync(0xffffffffu, erp[i], o);
            }
        }
        if ((tc & 3) == 0) {
            int head = blockIdx.x * 2 + (tc >> 2);
#pragma unroll
            for (int i = 0; i < 4; i++) {
                int r = blockRow + tr * 4 + i;
                if (r < M) {
                    g_el1[r * H1 + head] = elp[i];
                    g_er1[r * H1 + head] = erp[i];
                }
            }
        }
    } else {
        // reduce over all 8 tc lanes (xor 1,2,4)
#pragma unroll
        for (int i = 0; i < 4; i++) {
#pragma unroll
            for (int o = 1; o <= 4; o <<= 1) {
                elp[i] += __shfl_xor_sync(0xffffffffu, elp[i], o);
                erp[i] += __shfl_xor_sync(0xffffffffu, erp[i], o);
            }
        }
        if (tc == 0) {
#pragma unroll
            for (int i = 0; i < 4; i++) {
                int r = blockRow + tr * 4 + i;
                if (r < M) { g_el2[r] = elp[i]; g_er2[r] = erp[i]; }
            }
        }
    }
}

// ---------------- CSR build ----------------
__global__ void zero_cnt_kernel() {
    int i = blockIdx.x * blockDim.x + threadIdx.x;
    if (i < NNODES) g_cnt[i] = 0;
}

__global__ void hist_kernel(const int* __restrict__ dst) {
    int e = blockIdx.x * blockDim.x + threadIdx.x;
    if (e < NEDGES) atomicAdd(&g_cnt[dst[e]], 1);
}

__global__ void scan_kernel() {
    __shared__ int warpsum[32];
    int tid = threadIdx.x, lane = tid & 31, wid = tid >> 5;
    int carry = 0;
    for (int base = 0; base < NNODES; base += 4096) {
        int idx = base + tid * 4;
        int v0 = 0, v1 = 0, v2 = 0, v3 = 0;
        if (idx + 3 < NNODES) {
            int4 t = *(const int4*)&g_cnt[idx];
            v0 = t.x; v1 = t.y; v2 = t.z; v3 = t.w;
        } else {
            if (idx + 0 < NNODES) v0 = g_cnt[idx + 0];
            if (idx + 1 < NNODES) v1 = g_cnt[idx + 1];
            if (idx + 2 < NNODES) v2 = g_cnt[idx + 2];
            if (idx + 3 < NNODES) v3 = g_cnt[idx + 3];
        }
        int tsum = v0 + v1 + v2 + v3;
        int x = tsum;
#pragma unroll
        for (int o = 1; o < 32; o <<= 1) {
            int t = __shfl_up_sync(0xffffffffu, x, o);
            if (lane >= o) x += t;
        }
        if (lane == 31) warpsum[wid] = x;
        __syncthreads();
        if (wid == 0) {
            int w = warpsum[lane];
#pragma unroll
            for (int o = 1; o < 32; o <<= 1) {
                int t = __shfl_up_sync(0xffffffffu, w, o);
                if (lane >= o) w += t;
            }
            warpsum[lane] = w;
        }
        __syncthreads();
        int wexcl = (wid == 0) ? 0 : warpsum[wid - 1];
        int total = warpsum[31];
        int p = carry + wexcl + x - tsum;
        if (idx + 0 < NNODES) { g_off[idx + 0] = p;                g_cur[idx + 0] = p; }
        if (idx + 1 < NNODES) { g_off[idx + 1] = p + v0;           g_cur[idx + 1] = p + v0; }
        if (idx + 2 < NNODES) { g_off[idx + 2] = p + v0 + v1;      g_cur[idx + 2] = p + v0 + v1; }
        if (idx + 3 < NNODES) { g_off[idx + 3] = p + v0 + v1 + v2; g_cur[idx + 3] = p + v0 + v1 + v2; }
        carry += total;
        __syncthreads();
    }
    if (tid == 0) g_off[NNODES] = carry;
}

__global__ void scatter_kernel(const int* __restrict__ src, const int* __restrict__ dst) {
    int e = blockIdx.x * blockDim.x + threadIdx.x;
    if (e < NEDGES) {
        int p = atomicAdd(&g_cur[dst[e]], 1);
        g_csr_src[p] = src[e];
    }
}

// ---------------- layer 1 aggregation: warp per dst node (fp16 feats) ----------------
__global__ void agg1_kernel(const float* __restrict__ b1) {
    int n = (blockIdx.x * blockDim.x + threadIdx.x) >> 5;
    if (n >= NNODES) return;
    int lane = threadIdx.x & 31;
    int hh = lane >> 2;
    int db = (lane & 3) * 8;     // 8 half elements

    float ern = g_er1[n * H1 + hh];
    float wsum = 0.f;
    float a[8];
#pragma unroll
    for (int k = 0; k < 8; k++) a[k] = 0.f;

    int beg = g_off[n], end = g_off[n + 1];
    for (int e = beg; e < end; e++) {
        int s = g_csr_src[e];
        float x = g_el1[s * H1 + hh] + ern;
        x = fmaxf(x, 0.2f * x);          // leaky_relu(0.2)
        float wgt = __expf(x);
        wsum += wgt;
        uint4 hv = *(const uint4*)(g_feat1h + (size_t)s * HD1 + hh * HID + db);
        const __half2* hp = (const __half2*)&hv;
        float2 f0 = __half22float2(hp[0]);
        float2 f1 = __half22float2(hp[1]);
        float2 f2 = __half22float2(hp[2]);
        float2 f3 = __half22float2(hp[3]);
        a[0] += wgt * f0.x; a[1] += wgt * f0.y;
        a[2] += wgt * f1.x; a[3] += wgt * f1.y;
        a[4] += wgt * f2.x; a[5] += wgt * f2.y;
        a[6] += wgt * f3.x; a[7] += wgt * f3.y;
    }

    float inv = 1.f / wsum;
    float* o = g_h1 + (size_t)n * HD1 + hh * HID + db;
    const float* bp = b1 + hh * HID + db;
#pragma unroll
    for (int k = 0; k < 8; k++) {
        float v = a[k] * inv + bp[k];
        a[k] = v > 0.f ? v : (__expf(v) - 1.f);   // ELU
    }
    *(float4*)o = make_float4(a[0], a[1], a[2], a[3]);
    *(float4*)(o + 4) = make_float4(a[4], a[5], a[6], a[7]);
}

// ---------------- layer 2 aggregation ----------------
__global__ void agg2_kernel(const float* __restrict__ b2, float* __restrict__ out) {
    int n = (blockIdx.x * blockDim.x + threadIdx.x) >> 5;
    if (n >= NNODES) return;
    int lane = threadIdx.x & 31;

    float ern = g_er2[n];
    float wsum = 0.f;
    float a0 = 0.f, a1 = 0.f;

    int beg = g_off[n], end = g_off[n + 1];
    for (int e = beg; e < end; e++) {
        int s = g_csr_src[e];
        float x = g_el2[s] + ern;
        x = fmaxf(x, 0.2f * x);
        float wgt = __expf(x);
        wsum += wgt;
        float2 f = *(const float2*)(g_feat2 + (size_t)s * OUT_DIM + lane * 2);
        a0 += wgt * f.x;
        a1 += wgt * f.y;
    }

    float inv = 1.f / wsum;
    out[(size_t)n * OUT_DIM + lane * 2 + 0] = a0 * inv + b2[lane * 2 + 0];
    out[(size_t)n * OUT_DIM + lane * 2 + 1] = a1 * inv + b2[lane * 2 + 1];
}

// ---------------- launch ----------------
extern "C" void kernel_launch(void* const* d_in, const int* in_sizes, int n_in,
                              void* d_out, int out_size) {
    const float* h   = (const float*)d_in[0];
    const float* W1  = (const float*)d_in[1];
    const float* al1 = (const float*)d_in[2];
    const float* ar1 = (const float*)d_in[3];
    const float* b1  = (const float*)d_in[4];
    const float* W2  = (const float*)d_in[5];
    const float* al2 = (const float*)d_in[6];
    const float* ar2 = (const float*)d_in[7];
    const float* b2  = (const float*)d_in[8];
    const int*   src = (const int*)d_in[9];
    const int*   dst = (const int*)d_in[10];
    float* out = (float*)d_out;

    float* h1p;   cudaGetSymbolAddress((void**)&h1p, g_h1);
    float* feat2; cudaGetSymbolAddress((void**)&feat2, g_feat2);

    static cudaStream_t s_csr = nullptr;
    static cudaEvent_t ev_fork = nullptr, ev_join = nullptr;
    if (s_csr == nullptr) {
        cudaStreamCreateWithFlags(&s_csr, cudaStreamNonBlocking);
        cudaEventCreateWithFlags(&ev_fork, cudaEventDisableTiming);
        cudaEventCreateWithFlags(&ev_join, cudaEventDisableTiming);
    }

    const int nwarpblocks = (NNODES * 32 + 255) / 256;
    const int eblocks = (NEDGES + 255) / 256;

    // fork: CSR build concurrent with GEMM1.
    // Submission order puts gemm1 4th (the slot ncu's -s window has been capturing).
    cudaEventRecord(ev_fork, 0);
    cudaStreamWaitEvent(s_csr, ev_fork, 0);
    zero_cnt_kernel<<<(NNODES + 255) / 256, 256, 0, s_csr>>>();          // 1
    hist_kernel<<<eblocks, 256, 0, s_csr>>>(dst);                        // 2
    scan_kernel<<<1, 1024, 0, s_csr>>>();                                // 3
    {
        dim3 grid(HD1 / BNT, (NNODES + BMT - 1) / BMT);
        pgemm_kernel<1><<<grid, 256>>>(h, NNODES, HD1, W1, nullptr, al1, ar1);   // 4
    }
    scatter_kernel<<<eblocks, 256, 0, s_csr>>>(src, dst);                // 5
    cudaEventRecord(ev_join, s_csr);

    cudaStreamWaitEvent(0, ev_join, 0);
    agg1_kernel<<<nwarpblocks, 256>>>(b1);                               // 6

    {
        dim3 grid(OUT_DIM / BNT, (NNODES + BMT - 1) / BMT);
        pgemm_kernel<2><<<grid, 256>>>(h1p, NNODES, OUT_DIM, W2, feat2, al2, ar2); // 7
    }
    agg2_kernel<<<nwarpblocks, 256>>>(b2, out);                          // 8
}

// round 7
// speedup vs baseline: 1.7203x; 1.7203x over previous
#include <cuda_runtime.h>
#include <cuda_fp16.h>
#include <cstdint>

#define NNODES 50000
#define NEDGES 850000
#define IN_DIM 256
#define HID 32
#define H1 8
#define OUT_DIM 64
#define HD1 (H1*HID)   // 256
#define KDIM 256
#define ASTR 36        // 32 + 4 pad (floats)

// ---------------- scratch ----------------
__device__ __align__(16) __half g_feat1h[NNODES * HD1];   // 25.6 MB fp16
__device__ __align__(16) float  g_h1[NNODES * HD1];       // 51.2 MB
__device__ __align__(16) float  g_feat2[NNODES * OUT_DIM];
__device__ __align__(16) float  g_el1[NNODES * H1];
__device__ __align__(16) float  g_er1[NNODES * H1];
__device__ __align__(16) float  g_el2[NNODES];
__device__ __align__(16) float  g_er2[NNODES];
__device__ __align__(16) int    g_cnt[NNODES];
__device__ __align__(16) int    g_off[NNODES + 1];
__device__ __align__(16) int    g_cur[NNODES];
__device__ __align__(16) int    g_csr_src[NEDGES];

// packed f32x2 FMA: d.lo += a.lo*b.lo ; d.hi += a.hi*b.hi
#define FMA_X2(d, a, b) \
    asm("fma.rn.f32x2 %0, %1, %2, %0;" : "+l"(d) : "l"(a), "l"(b))

// cp.async 16B with zfill (sz = 16 valid, 0 -> fill zeros)
#define CPA16(dst, src, sz) \
    asm volatile("cp.async.cg.shared.global [%0], [%1], 16, %2;" :: "r"(dst), "l"(src), "r"(sz) : "memory")
#define CP_COMMIT() asm volatile("cp.async.commit_group;" ::: "memory")
#define CP_WAIT1()  asm volatile("cp.async.wait_group 1;" ::: "memory")

__device__ __forceinline__ uint32_t smem_u32(const void* p) {
    uint32_t a;
    asm("{ .reg .u64 t; cvta.to.shared.u64 t, %1; cvt.u32.u64 %0, t; }" : "=r"(a) : "l"(p));
    return a;
}
__device__ __forceinline__ unsigned long long pack2(float x) {
    unsigned long long r;
    asm("mov.b64 %0, {%1, %1};" : "=l"(r) : "f"(x));
    return r;
}
__device__ __forceinline__ uint32_t h2_bits(__half2 h) {
    uint32_t u;
    memcpy(&u, &h, 4);
    return u;
}

// ---------------- packed-fp32 GEMM, cp.async pipelined, fused attention epilogue ----------------
// Block: 128 rows x NT cols (NT = full width). 256 threads: tr=tid>>4 (16), tc=tid&15 (16).
// Thread microtile: rows {tr+16i, i<8}, cols {4tc+64q, q<NT/64}.
// LAYER 1 (NT=256): C -> fp16 g_feat1h; el1/er1 per 32-col head (head = 2q + tc>>3).
// LAYER 2 (NT=64):  C -> float Cout;    el2/er2 whole row.
template <int NT, int LAYER>
__global__ __launch_bounds__(256) void pgemm_kernel(
    const float* __restrict__ A, int M,
    const float* __restrict__ B,          // [KDIM][NT] row-major
    float* __restrict__ Cout,
    const float* __restrict__ al, const float* __restrict__ ar)
{
    constexpr int BSTR = NT + 4;
    constexpr int QN = NT / 64;
    extern __shared__ float smf[];
    float* Asm = smf;                        // [2][128][ASTR]
    float* Bsm = smf + 2 * 128 * ASTR;       // [2][32][BSTR]

    const int tid = threadIdx.x;
    const int lane = tid & 31;
    const int tc = tid & 15;
    const int tr = tid >> 4;
    const int blockRow = blockIdx.x * 128;

    // cp.async load mappings
    const int arow = tid >> 1;               // 0..127
    const int ak = (tid & 1) * 16;           // 0 or 16 (floats)
    const int brow = tid >> 3;               // 0..31
    const int bcol = (tid & 7) * (NT / 8);   // floats

    unsigned long long acc[8][QN][2];
#pragma unroll
    for (int i = 0; i < 8; i++)
#pragma unroll
        for (int q = 0; q < QN; q++) { acc[i][q][0] = 0ull; acc[i][q][1] = 0ull; }

    const int agr = blockRow + arow;
    const int asz = (agr < M) ? 16 : 0;
    const float* aSrcBase = A + (size_t)agr * KDIM + ak;
    const float* bSrcBase = B + (size_t)brow * NT + bcol;
    uint32_t aDst0 = smem_u32(Asm + arow * ASTR + ak);
    uint32_t bDst0 = smem_u32(Bsm + brow * BSTR + bcol);
    constexpr uint32_t ABUF = 128 * ASTR * 4;   // bytes
    constexpr uint32_t BBUF = 32 * BSTR * 4;

    // prologue: chunk 0 -> buf 0
    {
#pragma unroll
        for (int j = 0; j < 4; j++) CPA16(aDst0 + j * 16, aSrcBase + j * 4, asz);
#pragma unroll
        for (int j = 0; j < NT / 32; j++) CPA16(bDst0 + j * 16, bSrcBase + j * 4, 16);
        CP_COMMIT();
    }

    for (int c = 0; c < KDIM / 32; c++) {
        const int buf = c & 1;
        if (c < KDIM / 32 - 1) {
            const float* aSrc = aSrcBase + (c + 1) * 32;
            const float* bSrc = bSrcBase + (size_t)(c + 1) * 32 * NT;
            uint32_t aD = aDst0 + (buf ^ 1) * ABUF;
            uint32_t bD = bDst0 + (buf ^ 1) * BBUF;
#pragma unroll
            for (int j = 0; j < 4; j++) CPA16(aD + j * 16, aSrc + j * 4, asz);
#pragma unroll
            for (int j = 0; j < NT / 32; j++) CPA16(bD + j * 16, bSrc + j * 4, 16);
        }
        CP_COMMIT();
        CP_WAIT1();
        __syncthreads();

        const float* Ab = Asm + buf * 128 * ASTR;
        const float* Bb = Bsm + buf * 32 * BSTR;
#pragma unroll 4
        for (int kk = 0; kk < 32; kk++) {
            unsigned long long ap[8];
#pragma unroll
            for (int i = 0; i < 8; i++)
                ap[i] = pack2(Ab[(tr + 16 * i) * ASTR + kk]);
            unsigned long long bq[QN][2];
#pragma unroll
            for (int q = 0; q < QN; q++) {
                float4 bv = *(const float4*)&Bb[kk * BSTR + 4 * tc + 64 * q];
                memcpy(&bq[q][0], &bv.x, 8);
                memcpy(&bq[q][1], &bv.z, 8);
            }
#pragma unroll
            for (int i = 0; i < 8; i++)
#pragma unroll
                for (int q = 0; q < QN; q++) {
                    FMA_X2(acc[i][q][0], ap[i], bq[q][0]);
                    FMA_X2(acc[i][q][1], ap[i], bq[q][1]);
                }
        }
        __syncthreads();
    }

    // ---- epilogue: store C + fused el/er ----
#pragma unroll
    for (int i = 0; i < 8; i++) {
        const int r = blockRow + tr + 16 * i;
        const bool v = r < M;
#pragma unroll
        for (int q = 0; q < QN; q++) {
            float c0, c1, c2, c3;
            memcpy(&c0, (char*)&acc[i][q][0] + 0, 4);
            memcpy(&c1, (char*)&acc[i][q][0] + 4, 4);
            memcpy(&c2, (char*)&acc[i][q][1] + 0, 4);
            memcpy(&c3, (char*)&acc[i][q][1] + 4, 4);
            const int col = 4 * tc + 64 * q;
            float el = c0 * al[col] + c1 * al[col + 1] + c2 * al[col + 2] + c3 * al[col + 3];
            float er = c0 * ar[col] + c1 * ar[col + 1] + c2 * ar[col + 2] + c3 * ar[col + 3];

            if (v) {
                if (LAYER == 1) {
                    __half2 p0 = __floats2half2_rn(c0, c1);
                    __half2 p1 = __floats2half2_rn(c2, c3);
                    uint2 w = make_uint2(h2_bits(p0), h2_bits(p1));
                    *(uint2*)&g_feat1h[(size_t)r * HD1 + col] = w;
                } else {
                    *(float4*)&Cout[(size_t)r * OUT_DIM + col] = make_float4(c0, c1, c2, c3);
                }
            }

            if (LAYER == 1) {
#pragma unroll
                for (int o = 1; o <= 4; o <<= 1) {
                    el += __shfl_xor_sync(0xffffffffu, el, o);
                    er += __shfl_xor_sync(0xffffffffu, er, o);
                }
                if ((lane & 7) == 0 && v) {
                    int head = 2 * q + ((lane >> 3) & 1);
                    g_el1[r * H1 + head] = el;
                    g_er1[r * H1 + head] = er;
                }
            } else {
#pragma unroll
                for (int o = 1; o <= 8; o <<= 1) {
                    el += __shfl_xor_sync(0xffffffffu, el, o);
                    er += __shfl_xor_sync(0xffffffffu, er, o);
                }
                if ((lane & 15) == 0 && v) {
                    g_el2[r] = el;
                    g_er2[r] = er;
                }
            }
        }
    }
}

// ---------------- CSR build ----------------
__global__ void zero_cnt_kernel() {
    int i = blockIdx.x * blockDim.x + threadIdx.x;
    if (i < NNODES) g_cnt[i] = 0;
}

__global__ void hist_kernel(const int* __restrict__ dst) {
    int e = blockIdx.x * blockDim.x + threadIdx.x;
    if (e < NEDGES) atomicAdd(&g_cnt[dst[e]], 1);
}

__global__ void scan_kernel() {
    __shared__ int warpsum[32];
    int tid = threadIdx.x, lane = tid & 31, wid = tid >> 5;
    int carry = 0;
    for (int base = 0; base < NNODES; base += 4096) {
        int idx = base + tid * 4;
        int v0 = 0, v1 = 0, v2 = 0, v3 = 0;
        if (idx + 3 < NNODES) {
            int4 t = *(const int4*)&g_cnt[idx];
            v0 = t.x; v1 = t.y; v2 = t.z; v3 = t.w;
        } else {
            if (idx + 0 < NNODES) v0 = g_cnt[idx + 0];
            if (idx + 1 < NNODES) v1 = g_cnt[idx + 1];
            if (idx + 2 < NNODES) v2 = g_cnt[idx + 2];
            if (idx + 3 < NNODES) v3 = g_cnt[idx + 3];
        }
        int tsum = v0 + v1 + v2 + v3;
        int x = tsum;
#pragma unroll
        for (int o = 1; o < 32; o <<= 1) {
            int t = __shfl_up_sync(0xffffffffu, x, o);
            if (lane >= o) x += t;
        }
        if (lane == 31) warpsum[wid] = x;
        __syncthreads();
        if (wid == 0) {
            int w = warpsum[lane];
#pragma unroll
            for (int o = 1; o < 32; o <<= 1) {
                int t = __shfl_up_sync(0xffffffffu, w, o);
                if (lane >= o) w += t;
            }
            warpsum[lane] = w;
        }
        __syncthreads();
        int wexcl = (wid == 0) ? 0 : warpsum[wid - 1];
        int total = warpsum[31];
        int p = carry + wexcl + x - tsum;
        if (idx + 0 < NNODES) { g_off[idx + 0] = p;                g_cur[idx + 0] = p; }
        if (idx + 1 < NNODES) { g_off[idx + 1] = p + v0;           g_cur[idx + 1] = p + v0; }
        if (idx + 2 < NNODES) { g_off[idx + 2] = p + v0 + v1;      g_cur[idx + 2] = p + v0 + v1; }
        if (idx + 3 < NNODES) { g_off[idx + 3] = p + v0 + v1 + v2; g_cur[idx + 3] = p + v0 + v1 + v2; }
        carry += total;
        __syncthreads();
    }
    if (tid == 0) g_off[NNODES] = carry;
}

__global__ void scatter_kernel(const int* __restrict__ src, const int* __restrict__ dst) {
    int e = blockIdx.x * blockDim.x + threadIdx.x;
    if (e < NEDGES) {
        int p = atomicAdd(&g_cur[dst[e]], 1);
        g_csr_src[p] = src[e];
    }
}

// ---------------- layer 1 aggregation: warp per dst node (fp16 feats) ----------------
__global__ void agg1_kernel(const float* __restrict__ b1) {
    int n = (blockIdx.x * blockDim.x + threadIdx.x) >> 5;
    if (n >= NNODES) return;
    int lane = threadIdx.x & 31;
    int hh = lane >> 2;
    int db = (lane & 3) * 8;     // 8 half elements

    float ern = g_er1[n * H1 + hh];
    float wsum = 0.f;
    float a[8];
#pragma unroll
    for (int k = 0; k < 8; k++) a[k] = 0.f;

    int beg = g_off[n], end = g_off[n + 1];
    for (int e = beg; e < end; e++) {
        int s = g_csr_src[e];
        float x = g_el1[s * H1 + hh] + ern;
        x = fmaxf(x, 0.2f * x);          // leaky_relu(0.2)
        float wgt = __expf(x);
        wsum += wgt;
        uint4 hv = *(const uint4*)(g_feat1h + (size_t)s * HD1 + hh * HID + db);
        const __half2* hp = (const __half2*)&hv;
        float2 f0 = __half22float2(hp[0]);
        float2 f1 = __half22float2(hp[1]);
        float2 f2 = __half22float2(hp[2]);
        float2 f3 = __half22float2(hp[3]);
        a[0] += wgt * f0.x; a[1] += wgt * f0.y;
        a[2] += wgt * f1.x; a[3] += wgt * f1.y;
        a[4] += wgt * f2.x; a[5] += wgt * f2.y;
        a[6] += wgt * f3.x; a[7] += wgt * f3.y;
    }

    float inv = 1.f / wsum;
    float* o = g_h1 + (size_t)n * HD1 + hh * HID + db;
    const float* bp = b1 + hh * HID + db;
#pragma unroll
    for (int k = 0; k < 8; k++) {
        float v = a[k] * inv + bp[k];
        a[k] = v > 0.f ? v : (__expf(v) - 1.f);   // ELU
    }
    *(float4*)o = make_float4(a[0], a[1], a[2], a[3]);
    *(float4*)(o + 4) = make_float4(a[4], a[5], a[6], a[7]);
}

// ---------------- layer 2 aggregation ----------------
__global__ void agg2_kernel(const float* __restrict__ b2, float* __restrict__ out) {
    int n = (blockIdx.x * blockDim.x + threadIdx.x) >> 5;
    if (n >= NNODES) return;
    int lane = threadIdx.x & 31;

    float ern = g_er2[n];
    float wsum = 0.f;
    float a0 = 0.f, a1 = 0.f;

    int beg = g_off[n], end = g_off[n + 1];
    for (int e = beg; e < end; e++) {
        int s = g_csr_src[e];
        float x = g_el2[s] + ern;
        x = fmaxf(x, 0.2f * x);
        float wgt = __expf(x);
        wsum += wgt;
        float2 f = *(const float2*)(g_feat2 + (size_t)s * OUT_DIM + lane * 2);
        a0 += wgt * f.x;
        a1 += wgt * f.y;
    }

    float inv = 1.f / wsum;
    out[(size_t)n * OUT_DIM + lane * 2 + 0] = a0 * inv + b2[lane * 2 + 0];
    out[(size_t)n * OUT_DIM + lane * 2 + 1] = a1 * inv + b2[lane * 2 + 1];
}

// ---------------- launch ----------------
extern "C" void kernel_launch(void* const* d_in, const int* in_sizes, int n_in,
                              void* d_out, int out_size) {
    const float* h   = (const float*)d_in[0];
    const float* W1  = (const float*)d_in[1];
    const float* al1 = (const float*)d_in[2];
    const float* ar1 = (const float*)d_in[3];
    const float* b1  = (const float*)d_in[4];
    const float* W2  = (const float*)d_in[5];
    const float* al2 = (const float*)d_in[6];
    const float* ar2 = (const float*)d_in[7];
    const float* b2  = (const float*)d_in[8];
    const int*   src = (const int*)d_in[9];
    const int*   dst = (const int*)d_in[10];
    float* out = (float*)d_out;

    float* h1p;   cudaGetSymbolAddress((void**)&h1p, g_h1);
    float* feat2; cudaGetSymbolAddress((void**)&feat2, g_feat2);

    const int SMEM1 = 2 * 128 * ASTR * 4 + 2 * 32 * (256 + 4) * 4;   // 103424
    const int SMEM2 = 2 * 128 * ASTR * 4 + 2 * 32 * (64 + 4) * 4;    // 54272
    static bool attr_done = false;
    if (!attr_done) {
        cudaFuncSetAttribute(pgemm_kernel<256, 1>, cudaFuncAttributeMaxDynamicSharedMemorySize, SMEM1);
        cudaFuncSetAttribute(pgemm_kernel<64, 2>,  cudaFuncAttributeMaxDynamicSharedMemorySize, SMEM2);
        attr_done = true;
    }

    static cudaStream_t s_csr = nullptr;
    static cudaEvent_t ev_fork = nullptr, ev_join = nullptr;
    if (s_csr == nullptr) {
        cudaStreamCreateWithFlags(&s_csr, cudaStreamNonBlocking);
        cudaEventCreateWithFlags(&ev_fork, cudaEventDisableTiming);
        cudaEventCreateWithFlags(&ev_join, cudaEventDisableTiming);
    }

    const int nwarpblocks = (NNODES * 32 + 255) / 256;
    const int eblocks = (NEDGES + 255) / 256;
    const int gblocks = (NNODES + 127) / 128;   // 391

    // fork: CSR build concurrent with GEMM1; gemm1 stays 4th submission for ncu window
    cudaEventRecord(ev_fork, 0);
    cudaStreamWaitEvent(s_csr, ev_fork, 0);
    zero_cnt_kernel<<<(NNODES + 255) / 256, 256, 0, s_csr>>>();          // 1
    hist_kernel<<<eblocks, 256, 0, s_csr>>>(dst);                        // 2
    scan_kernel<<<1, 1024, 0, s_csr>>>();                                // 3
    pgemm_kernel<256, 1><<<gblocks, 256, SMEM1>>>(h, NNODES, W1, nullptr, al1, ar1);   // 4
    scatter_kernel<<<eblocks, 256, 0, s_csr>>>(src, dst);                // 5
    cudaEventRecord(ev_join, s_csr);

    cudaStreamWaitEvent(0, ev_join, 0);
    agg1_kernel<<<nwarpblocks, 256>>>(b1);                               // 6

    pgemm_kernel<64, 2><<<gblocks, 256, SMEM2>>>(h1p, NNODES, W2, feat2, al2, ar2);    // 7
    agg2_kernel<<<nwarpblocks, 256>>>(b2, out);                          // 8
}